// round 13
// baseline (speedup 1.0000x reference)
#include <cuda_runtime.h>
#include <cuda_fp16.h>

#define ERRF 1e-12f
constexpr int LEN = 2048;
constexpr int DIM = 64;
constexpr int NT  = 16;
constexpr int BHN = 32;

// Prepacked fp16 operands, row-major [bh][row][64], 128B per row.
__device__ __half g_Ah[BHN * LEN * DIM];   // k*sqrt(src)  hi
__device__ __half g_Al[BHN * LEN * DIM];   // k*sqrt(src)  lo
__device__ __half g_Bh[BHN * LEN * DIM];   // k*sqrt(dest) fp16

// smem: just two 16KB buffers (B double-buffer; A borrows them in the prologue)
constexpr int OFF_BUF1 = 16384;
constexpr int SMEM_TOTAL = 32768;   // 32 KB -> 6 CTAs/SM (smem); regs cap 85

#define SWZ(o) ((o) ^ (((o) >> 3) & 0x70))

__device__ __forceinline__ unsigned smem_u32(const void* p) {
    return (unsigned)__cvta_generic_to_shared(p);
}
__device__ __forceinline__ float fast_lg2(float x) { float y; asm("lg2.approx.f32 %0, %1;" : "=f"(y) : "f"(x)); return y; }
__device__ __forceinline__ float fast_ex2(float x) { float y; asm("ex2.approx.f32 %0, %1;" : "=f"(y) : "f"(x)); return y; }
__device__ __forceinline__ float pow23(float x) {
    return fast_ex2(fast_lg2(fmaxf(x, ERRF)) * 0.66666667f);
}

__device__ __forceinline__ void ldsm4(unsigned addr, unsigned& r0, unsigned& r1, unsigned& r2, unsigned& r3) {
    asm volatile("ldmatrix.sync.aligned.m8n8.x4.shared.b16 {%0,%1,%2,%3}, [%4];"
                 : "=r"(r0), "=r"(r1), "=r"(r2), "=r"(r3) : "r"(addr));
}

__device__ __forceinline__ void mma16816(float* c, const unsigned* a, unsigned b0, unsigned b1) {
    asm volatile("mma.sync.aligned.m16n8k16.row.col.f32.f16.f16.f32 "
                 "{%0,%1,%2,%3}, {%4,%5,%6,%7}, {%8,%9}, {%0,%1,%2,%3};"
                 : "+f"(c[0]), "+f"(c[1]), "+f"(c[2]), "+f"(c[3])
                 : "r"(a[0]), "r"(a[1]), "r"(a[2]), "r"(a[3]), "r"(b0), "r"(b1));
}
__device__ __forceinline__ void mma16816_z(float* c, const unsigned* a, unsigned b0, unsigned b1) {
    asm volatile("mma.sync.aligned.m16n8k16.row.col.f32.f16.f16.f32 "
                 "{%0,%1,%2,%3}, {%4,%5,%6,%7}, {%8,%9}, {%10,%10,%10,%10};"
                 : "=f"(c[0]), "=f"(c[1]), "=f"(c[2]), "=f"(c[3])
                 : "r"(a[0]), "r"(a[1]), "r"(a[2]), "r"(a[3]), "r"(b0), "r"(b1), "f"(0.f));
}

__device__ __forceinline__ void cp16(unsigned sdst, const void* gsrc) {
    asm volatile("cp.async.cg.shared.global [%0], [%1], 16;" :: "r"(sdst), "l"(gsrc) : "memory");
}
__device__ __forceinline__ void cp_commit() { asm volatile("cp.async.commit_group;" ::: "memory"); }
__device__ __forceinline__ void cp_wait0()  { asm volatile("cp.async.wait_group 0;" ::: "memory"); }

__device__ __forceinline__ void stcs4(float* p, float4 v) {
    asm volatile("st.global.cs.v4.f32 [%0], {%1,%2,%3,%4};"
                 :: "l"(p), "f"(v.x), "f"(v.y), "f"(v.z), "f"(v.w) : "memory");
}
__device__ __forceinline__ void stcs4_zero(float* p) {
    asm volatile("st.global.cs.v4.f32 [%0], {%1, %1, %1, %1};" :: "l"(p), "f"(0.f) : "memory");
}

// ---------------- prep kernel: fp32 -> scaled fp16 hi/lo ----------------
__global__ void __launch_bounds__(256)
prep_kernel(const float* __restrict__ k, const float* __restrict__ src,
            const float* __restrict__ dst)
{
    const int idx = blockIdx.x * 256 + threadIdx.x;
    const int row = idx >> 2;
    const int q   = idx & 3;
    const float ws = sqrtf(src[row] + ERRF);
    const float wd = sqrtf(dst[row] + ERRF);
    const float4* kp = reinterpret_cast<const float4*>(k + (size_t)row * DIM + q * 16);

    __half2 oh[8], ol[8], ob[8];
    #pragma unroll
    for (int p = 0; p < 4; ++p) {
        float4 v = kp[p];
        float a0 = v.x * ws, a1 = v.y * ws, a2 = v.z * ws, a3 = v.w * ws;
        __half h0 = __float2half_rn(a0), h1 = __float2half_rn(a1);
        __half h2 = __float2half_rn(a2), h3 = __float2half_rn(a3);
        oh[p * 2]     = __half2(h0, h1);
        oh[p * 2 + 1] = __half2(h2, h3);
        ol[p * 2]     = __floats2half2_rn(a0 - __half2float(h0), a1 - __half2float(h1));
        ol[p * 2 + 1] = __floats2half2_rn(a2 - __half2float(h2), a3 - __half2float(h3));
        ob[p * 2]     = __floats2half2_rn(v.x * wd, v.y * wd);
        ob[p * 2 + 1] = __floats2half2_rn(v.z * wd, v.w * wd);
    }
    const size_t o = (size_t)row * DIM + q * 16;
    uint4* dAh = reinterpret_cast<uint4*>(g_Ah + o);
    uint4* dAl = reinterpret_cast<uint4*>(g_Al + o);
    uint4* dBh = reinterpret_cast<uint4*>(g_Bh + o);
    const uint4* sh = reinterpret_cast<const uint4*>(oh);
    const uint4* sl = reinterpret_cast<const uint4*>(ol);
    const uint4* sb = reinterpret_cast<const uint4*>(ob);
    dAh[0] = sh[0]; dAh[1] = sh[1];
    dAl[0] = sl[0]; dAl[1] = sl[1];
    dBh[0] = sb[0]; dBh[1] = sb[1];
}

// B tile copy with column-coalescing row permutation:
// within each 16-row group, true row t -> position [0,1,8,9,2,3,10,11,4,5,12,13,6,7,14,15]
__device__ __forceinline__ void cp_tile16_perm(const char* gsrc, unsigned sdst, int tid) {
    #pragma unroll
    for (int i = 0; i < 8; ++i) {
        int cid = tid + 128 * i;
        int row = cid >> 3;
        int pr  = (row & ~15) | ((row & 2) << 2) | ((row >> 1) & 6) | (row & 1);
        unsigned dst = (unsigned)(pr * 128 + (cid & 7) * 16);
        cp16(sdst + SWZ(dst), gsrc + (unsigned)(cid << 4));
    }
}
// A tile (8KB, 64 rows), no permutation
__device__ __forceinline__ void cp_tile8(const char* gsrc, unsigned sdst, int tid) {
    #pragma unroll
    for (int i = 0; i < 4; ++i) {
        int cid = tid + 128 * i;
        unsigned off = (unsigned)(cid << 4);
        cp16(sdst + SWZ(off), gsrc + off);
    }
}

// ---------------- main kernel: 128 threads, 64-row i-tile, 6 CTAs/SM ----------------
__global__ void __launch_bounds__(128, 6)
mha_hmma9_kernel(float* __restrict__ out)
{
    extern __shared__ char smem[];
    const int tid = threadIdx.x;
    const int wid = tid >> 5;
    const int lid = tid & 31;
    const int bh  = blockIdx.y;
    const int diag = blockIdx.x >> 1;
    const int it0 = blockIdx.x * 64;

    float* ob = out + (size_t)bh * LEN * LEN;
    const char* gA  = reinterpret_cast<const char*>(g_Ah + ((size_t)bh * LEN + it0) * DIM);
    const char* gAl = reinterpret_cast<const char*>(g_Al + ((size_t)bh * LEN + it0) * DIM);
    const char* gB  = reinterpret_cast<const char*>(g_Bh + (size_t)bh * LEN * DIM);

    const unsigned sbase = smem_u32(smem);

    // ---- prologue: A hi -> buf0, A lo -> buf1; extract fragments; then B0 -> buf0 ----
    cp_tile8(gA,  sbase, tid);
    cp_tile8(gAl, sbase + OFF_BUF1, tid);
    cp_commit();
    cp_wait0();
    __syncthreads();

    const int l7  = lid & 7;
    const int sel = lid >> 3;
    const unsigned xk = (unsigned)(l7 << 4);
    const int arow  = wid * 16 + l7 + ((sel & 1) ? 8 : 0);
    const unsigned akoff = (sel & 2) ? 16u : 0u;
    const int bn    = l7 + ((sel & 2) ? 8 : 0);
    const unsigned bkoff = (sel & 1) ? 16u : 0u;
    const unsigned a_lane = sbase + (unsigned)(arow * 128);
    const unsigned b_lane = sbase + (unsigned)(bn * 128);

    unsigned ah[4][4], al[4][4];
    #pragma unroll
    for (int ks = 0; ks < 4; ++ks) {
        const unsigned ak = ((unsigned)(ks * 32) + akoff) ^ xk;
        ldsm4(a_lane + ak, ah[ks][0], ah[ks][1], ah[ks][2], ah[ks][3]);
        ldsm4(a_lane + OFF_BUF1 + ak, al[ks][0], al[ks][1], al[ks][2], al[ks][3]);
    }
    __syncthreads();   // all warps done reading A from smem

    cp_tile16_perm(gB, sbase, tid);   // B tile 0 -> buf0
    cp_commit();
    cp_wait0();
    __syncthreads();

    // epilogue lane mapping: for fragment pair (2m,2m+1), lane q owns TRUE cols 16m+4q..+3
    const int q  = lid & 3;
    const int g4 = lid >> 2;
    const int gi_lo = it0 + wid * 16 + g4;
    const int gi_hi = gi_lo + 8;
    float* const row_lo = ob + (size_t)gi_lo * LEN;
    float* const row_hi = ob + (size_t)gi_hi * LEN;

    float carry_lo = 0.f, carry_hi = 0.f;
    float part_lo = 0.f,  part_hi = 0.f;

    for (int jt = 0; jt < NT; ++jt) {
        const int jb0 = jt * 128;
        const bool below = (jt < diag);
        const int nxt = jt + 1;

        if (nxt < NT) {
            cp_tile16_perm(gB + (size_t)nxt * 16384, sbase + (nxt & 1) * OFF_BUF1, tid);
            cp_commit();
        }

        if (below) {
            float* base = ob + (size_t)(it0 + wid * 16) * LEN + jb0 + lid * 4;
            #pragma unroll
            for (int r = 0; r < 16; ++r)
                stcs4_zero(base + (size_t)r * LEN);
        }

        // lane-partials -> full-row carry at the diagonal tile (before its stores)
        if (jt == diag) {
            float v = part_lo;
            v += __shfl_xor_sync(0xffffffffu, v, 1, 4);
            v += __shfl_xor_sync(0xffffffffu, v, 2, 4);
            carry_lo = v;
            v = part_hi;
            v += __shfl_xor_sync(0xffffffffu, v, 1, 4);
            v += __shfl_xor_sync(0xffffffffu, v, 2, 4);
            carry_hi = v;
        }

        const unsigned bb = sbase + (unsigned)((jt & 1) * OFF_BUF1) + (unsigned)(bn * 128);

        // ---- fused GEMM + epilogue, one 16-col fragment pair at a time ----
        #pragma unroll
        for (int m = 0; m < 8; ++m) {
            float c0[4], c1[4];
            #pragma unroll
            for (int ks = 0; ks < 4; ++ks) {
                unsigned b0, b1, b2, b3;
                ldsm4(bb + (unsigned)(m * 2048) + (((unsigned)(ks * 32) + bkoff) ^ xk),
                      b0, b1, b2, b3);
                if (ks == 0) {
                    mma16816_z(c0, ah[0], b0, b1);
                    mma16816_z(c1, ah[0], b2, b3);
                } else {
                    mma16816(c0, ah[ks], b0, b1);
                    mma16816(c1, ah[ks], b2, b3);
                }
                if (!below) {
                    mma16816(c0, al[ks], b0, b1);
                    mma16816(c1, al[ks], b2, b3);
                }
            }

            float t0 = pow23(c0[0]), t1 = pow23(c0[1]);
            float t2 = pow23(c1[0]), t3 = pow23(c1[1]);
            float u0 = pow23(c0[2]), u1 = pow23(c0[3]);
            float u2 = pow23(c1[2]), u3 = pow23(c1[3]);

            if (below) {
                part_lo += (t0 + t1) + (t2 + t3);
                part_hi += (u0 + u1) + (u2 + u3);
            } else {
                const int col0 = jb0 + m * 16 + q * 4;
                {
                    float s = t0 + t1 + t2 + t3, p = s, o;
                    o = __shfl_up_sync(0xffffffffu, p, 1, 4); if (q >= 1) p += o;
                    o = __shfl_up_sync(0xffffffffu, p, 2, 4); if (q >= 2) p += o;
                    float tot = __shfl_sync(0xffffffffu, p, 3, 4);
                    float e = carry_lo + (p - s);
                    float o0 = e + t0, o1 = o0 + t1, o2 = o1 + t2, o3 = o2 + t3;
                    carry_lo += tot;
                    float4 st;
                    if (jt == diag)
                        st = make_float4(col0 >= gi_lo ? o0 : 0.f,
                                         col0 + 1 >= gi_lo ? o1 : 0.f,
                                         col0 + 2 >= gi_lo ? o2 : 0.f,
                                         col0 + 3 >= gi_lo ? o3 : 0.f);
                    else
                        st = make_float4(o0, o1, o2, o3);
                    stcs4(row_lo + col0, st);
                }
                {
                    float s = u0 + u1 + u2 + u3, p = s, o;
                    o = __shfl_up_sync(0xffffffffu, p, 1, 4); if (q >= 1) p += o;
                    o = __shfl_up_sync(0xffffffffu, p, 2, 4); if (q >= 2) p += o;
                    float tot = __shfl_sync(0xffffffffu, p, 3, 4);
                    float e = carry_hi + (p - s);
                    float o0 = e + u0, o1 = o0 + u1, o2 = o1 + u2, o3 = o2 + u3;
                    carry_hi += tot;
                    float4 st;
                    if (jt == diag)
                        st = make_float4(col0 >= gi_hi ? o0 : 0.f,
                                         col0 + 1 >= gi_hi ? o1 : 0.f,
                                         col0 + 2 >= gi_hi ? o2 : 0.f,
                                         col0 + 3 >= gi_hi ? o3 : 0.f);
                    else
                        st = make_float4(o0, o1, o2, o3);
                    stcs4(row_hi + col0, st);
                }
            }
        }

        if (nxt < NT) cp_wait0();
        __syncthreads();
    }
}

extern "C" void kernel_launch(void* const* d_in, const int* in_sizes, int n_in,
                              void* d_out, int out_size) {
    const float* k   = (const float*)d_in[0];
    const float* src = (const float*)d_in[1];
    const float* dst = (const float*)d_in[2];
    float*       out = (float*)d_out;

    cudaFuncSetAttribute(mha_hmma9_kernel,
                         cudaFuncAttributeMaxDynamicSharedMemorySize, SMEM_TOTAL);
    (void)in_sizes; (void)n_in; (void)out_size;

    prep_kernel<<<BHN * LEN * 4 / 256, 256>>>(k, src, dst);
    dim3 grid(LEN / 64, BHN);
    mha_hmma9_kernel<<<grid, 128, SMEM_TOTAL>>>(out);
}

// round 14
// speedup vs baseline: 1.0532x; 1.0532x over previous
#include <cuda_runtime.h>
#include <cuda_fp16.h>

#define ERRF 1e-12f
constexpr int LEN = 2048;
constexpr int DIM = 64;
constexpr int NT  = 16;
constexpr int BHN = 32;

// Prepacked fp16 operands, row-major [bh][row][64], 128B per row.
__device__ __half g_Ah[BHN * LEN * DIM];   // k*sqrt(src)  hi
__device__ __half g_Al[BHN * LEN * DIM];   // k*sqrt(src)  lo
__device__ __half g_Bh[BHN * LEN * DIM];   // k*sqrt(dest) fp16

// smem: two 16KB buffers (B double-buffer; A borrows them in the prologue)
constexpr int OFF_BUF1 = 16384;
constexpr int SMEM_TOTAL = 32768;

#define SWZ(o) ((o) ^ (((o) >> 3) & 0x70))

__device__ __forceinline__ unsigned smem_u32(const void* p) {
    return (unsigned)__cvta_generic_to_shared(p);
}
__device__ __forceinline__ float fast_lg2(float x) { float y; asm("lg2.approx.f32 %0, %1;" : "=f"(y) : "f"(x)); return y; }
__device__ __forceinline__ float fast_ex2(float x) { float y; asm("ex2.approx.f32 %0, %1;" : "=f"(y) : "f"(x)); return y; }
__device__ __forceinline__ float pow23(float x) {
    return fast_ex2(fast_lg2(fmaxf(x, ERRF)) * 0.66666667f);
}

__device__ __forceinline__ void ldsm4(unsigned addr, unsigned& r0, unsigned& r1, unsigned& r2, unsigned& r3) {
    asm volatile("ldmatrix.sync.aligned.m8n8.x4.shared.b16 {%0,%1,%2,%3}, [%4];"
                 : "=r"(r0), "=r"(r1), "=r"(r2), "=r"(r3) : "r"(addr));
}

__device__ __forceinline__ void mma16816(float* c, const unsigned* a, unsigned b0, unsigned b1) {
    asm volatile("mma.sync.aligned.m16n8k16.row.col.f32.f16.f16.f32 "
                 "{%0,%1,%2,%3}, {%4,%5,%6,%7}, {%8,%9}, {%0,%1,%2,%3};"
                 : "+f"(c[0]), "+f"(c[1]), "+f"(c[2]), "+f"(c[3])
                 : "r"(a[0]), "r"(a[1]), "r"(a[2]), "r"(a[3]), "r"(b0), "r"(b1));
}
__device__ __forceinline__ void mma16816_z(float* c, const unsigned* a, unsigned b0, unsigned b1) {
    asm volatile("mma.sync.aligned.m16n8k16.row.col.f32.f16.f16.f32 "
                 "{%0,%1,%2,%3}, {%4,%5,%6,%7}, {%8,%9}, {%10,%10,%10,%10};"
                 : "=f"(c[0]), "=f"(c[1]), "=f"(c[2]), "=f"(c[3])
                 : "r"(a[0]), "r"(a[1]), "r"(a[2]), "r"(a[3]), "r"(b0), "r"(b1), "f"(0.f));
}

__device__ __forceinline__ void cp16(unsigned sdst, const void* gsrc) {
    asm volatile("cp.async.cg.shared.global [%0], [%1], 16;" :: "r"(sdst), "l"(gsrc) : "memory");
}
__device__ __forceinline__ void cp_commit() { asm volatile("cp.async.commit_group;" ::: "memory"); }
__device__ __forceinline__ void cp_wait0()  { asm volatile("cp.async.wait_group 0;" ::: "memory"); }

__device__ __forceinline__ void stcs4(float* p, float4 v) {
    asm volatile("st.global.cs.v4.f32 [%0], {%1,%2,%3,%4};"
                 :: "l"(p), "f"(v.x), "f"(v.y), "f"(v.z), "f"(v.w) : "memory");
}
__device__ __forceinline__ void stcs4_zero(float* p) {
    asm volatile("st.global.cs.v4.f32 [%0], {%1, %1, %1, %1};" :: "l"(p), "f"(0.f) : "memory");
}

// ---------------- prep kernel: fp32 -> scaled fp16 hi/lo ----------------
__global__ void __launch_bounds__(256)
prep_kernel(const float* __restrict__ k, const float* __restrict__ src,
            const float* __restrict__ dst)
{
    const int idx = blockIdx.x * 256 + threadIdx.x;
    const int row = idx >> 2;
    const int q   = idx & 3;
    const float ws = sqrtf(src[row] + ERRF);
    const float wd = sqrtf(dst[row] + ERRF);
    const float4* kp = reinterpret_cast<const float4*>(k + (size_t)row * DIM + q * 16);

    __half2 oh[8], ol[8], ob[8];
    #pragma unroll
    for (int p = 0; p < 4; ++p) {
        float4 v = kp[p];
        float a0 = v.x * ws, a1 = v.y * ws, a2 = v.z * ws, a3 = v.w * ws;
        __half h0 = __float2half_rn(a0), h1 = __float2half_rn(a1);
        __half h2 = __float2half_rn(a2), h3 = __float2half_rn(a3);
        oh[p * 2]     = __half2(h0, h1);
        oh[p * 2 + 1] = __half2(h2, h3);
        ol[p * 2]     = __floats2half2_rn(a0 - __half2float(h0), a1 - __half2float(h1));
        ol[p * 2 + 1] = __floats2half2_rn(a2 - __half2float(h2), a3 - __half2float(h3));
        ob[p * 2]     = __floats2half2_rn(v.x * wd, v.y * wd);
        ob[p * 2 + 1] = __floats2half2_rn(v.z * wd, v.w * wd);
    }
    const size_t o = (size_t)row * DIM + q * 16;
    uint4* dAh = reinterpret_cast<uint4*>(g_Ah + o);
    uint4* dAl = reinterpret_cast<uint4*>(g_Al + o);
    uint4* dBh = reinterpret_cast<uint4*>(g_Bh + o);
    const uint4* sh = reinterpret_cast<const uint4*>(oh);
    const uint4* sl = reinterpret_cast<const uint4*>(ol);
    const uint4* sb = reinterpret_cast<const uint4*>(ob);
    dAh[0] = sh[0]; dAh[1] = sh[1];
    dAl[0] = sl[0]; dAl[1] = sl[1];
    dBh[0] = sb[0]; dBh[1] = sb[1];
}

// B tile copy with column-coalescing row permutation:
// within each 16-row group, true row t -> position [0,1,8,9,2,3,10,11,4,5,12,13,6,7,14,15]
__device__ __forceinline__ void cp_tile16_perm(const char* gsrc, unsigned sdst, int tid) {
    #pragma unroll
    for (int i = 0; i < 8; ++i) {
        int cid = tid + 128 * i;
        int row = cid >> 3;
        int pr  = (row & ~15) | ((row & 2) << 2) | ((row >> 1) & 6) | (row & 1);
        unsigned dst = (unsigned)(pr * 128 + (cid & 7) * 16);
        cp16(sdst + SWZ(dst), gsrc + (unsigned)(cid << 4));
    }
}
// A tile (8KB, 64 rows), no permutation
__device__ __forceinline__ void cp_tile8(const char* gsrc, unsigned sdst, int tid) {
    #pragma unroll
    for (int i = 0; i < 4; ++i) {
        int cid = tid + 128 * i;
        unsigned off = (unsigned)(cid << 4);
        cp16(sdst + SWZ(off), gsrc + off);
    }
}

// ---------------- main kernel: 128 threads, 64-row i-tile, 5 CTAs/SM ----------------
__global__ void __launch_bounds__(128, 5)
mha_hmma10_kernel(float* __restrict__ out)
{
    extern __shared__ char smem[];
    const int tid = threadIdx.x;
    const int wid = tid >> 5;
    const int lid = tid & 31;
    const int bh  = blockIdx.y;
    const int diag = blockIdx.x >> 1;
    const int it0 = blockIdx.x * 64;

    float* ob = out + (size_t)bh * LEN * LEN;
    const char* gA  = reinterpret_cast<const char*>(g_Ah + ((size_t)bh * LEN + it0) * DIM);
    const char* gAl = reinterpret_cast<const char*>(g_Al + ((size_t)bh * LEN + it0) * DIM);
    const char* gB  = reinterpret_cast<const char*>(g_Bh + (size_t)bh * LEN * DIM);

    const unsigned sbase = smem_u32(smem);

    // ---- prologue: A hi -> buf0, A lo -> buf1; extract fragments; then B0 -> buf0 ----
    cp_tile8(gA,  sbase, tid);
    cp_tile8(gAl, sbase + OFF_BUF1, tid);
    cp_commit();
    cp_wait0();
    __syncthreads();

    const int l7  = lid & 7;
    const int sel = lid >> 3;
    const unsigned xk = (unsigned)(l7 << 4);
    const int arow  = wid * 16 + l7 + ((sel & 1) ? 8 : 0);
    const unsigned akoff = (sel & 2) ? 16u : 0u;
    const int bn    = l7 + ((sel & 2) ? 8 : 0);
    const unsigned bkoff = (sel & 1) ? 16u : 0u;
    const unsigned a_lane = sbase + (unsigned)(arow * 128);

    unsigned ah[4][4], al[4][4];
    #pragma unroll
    for (int ks = 0; ks < 4; ++ks) {
        const unsigned ak = ((unsigned)(ks * 32) + akoff) ^ xk;
        ldsm4(a_lane + ak, ah[ks][0], ah[ks][1], ah[ks][2], ah[ks][3]);
        ldsm4(a_lane + OFF_BUF1 + ak, al[ks][0], al[ks][1], al[ks][2], al[ks][3]);
    }
    __syncthreads();   // all warps done reading A from smem

    cp_tile16_perm(gB, sbase, tid);   // B tile 0 -> buf0
    cp_commit();
    cp_wait0();
    __syncthreads();

    // epilogue lane mapping: for fragment pair (2m,2m+1), lane q owns TRUE cols 16m+4q..+3
    const int q  = lid & 3;
    const int g4 = lid >> 2;
    const int gi_lo = it0 + wid * 16 + g4;
    const int gi_hi = gi_lo + 8;
    float* const row_lo = ob + (size_t)gi_lo * LEN;
    float* const row_hi = ob + (size_t)gi_hi * LEN;

    float carry_lo = 0.f, carry_hi = 0.f;
    float part_lo = 0.f,  part_hi = 0.f;

    for (int jt = 0; jt < NT; ++jt) {
        const int jb0 = jt * 128;
        const bool below = (jt < diag);
        const int nxt = jt + 1;

        if (nxt < NT) {
            cp_tile16_perm(gB + (size_t)nxt * 16384, sbase + (nxt & 1) * OFF_BUF1, tid);
            cp_commit();
        }

        if (below) {
            float* base = ob + (size_t)(it0 + wid * 16) * LEN + jb0 + lid * 4;
            #pragma unroll
            for (int r = 0; r < 16; ++r)
                stcs4_zero(base + (size_t)r * LEN);
        }

        // lane-partials -> full-row carry at the diagonal tile (before its stores)
        if (jt == diag) {
            float v = part_lo;
            v += __shfl_xor_sync(0xffffffffu, v, 1, 4);
            v += __shfl_xor_sync(0xffffffffu, v, 2, 4);
            carry_lo = v;
            v = part_hi;
            v += __shfl_xor_sync(0xffffffffu, v, 1, 4);
            v += __shfl_xor_sync(0xffffffffu, v, 2, 4);
            carry_hi = v;
        }

        const unsigned bb = sbase + (unsigned)((jt & 1) * OFF_BUF1) + (unsigned)(bn * 128);

        // ---- half-tile fused: GEMM for 4 pairs (32 acc regs of ILP), then their epilogue ----
        #pragma unroll
        for (int h = 0; h < 2; ++h) {
            float c[4][2][4];
            #pragma unroll
            for (int ks = 0; ks < 4; ++ks) {
                const unsigned bkb = ((unsigned)(ks * 32) + bkoff) ^ xk;
                #pragma unroll
                for (int mm = 0; mm < 4; ++mm) {
                    const int m = h * 4 + mm;
                    unsigned b0, b1, b2, b3;
                    ldsm4(bb + (unsigned)(m * 2048) + bkb, b0, b1, b2, b3);
                    if (ks == 0) {
                        mma16816_z(c[mm][0], ah[0], b0, b1);
                        mma16816_z(c[mm][1], ah[0], b2, b3);
                    } else {
                        mma16816(c[mm][0], ah[ks], b0, b1);
                        mma16816(c[mm][1], ah[ks], b2, b3);
                    }
                    if (!below) {
                        mma16816(c[mm][0], al[ks], b0, b1);
                        mma16816(c[mm][1], al[ks], b2, b3);
                    }
                }
            }

            if (below) {
                #pragma unroll
                for (int mm = 0; mm < 4; ++mm) {
                    part_lo += pow23(c[mm][0][0]) + pow23(c[mm][0][1])
                             + pow23(c[mm][1][0]) + pow23(c[mm][1][1]);
                    part_hi += pow23(c[mm][0][2]) + pow23(c[mm][0][3])
                             + pow23(c[mm][1][2]) + pow23(c[mm][1][3]);
                }
            } else {
                #pragma unroll
                for (int mm = 0; mm < 4; ++mm) {
                    const int m = h * 4 + mm;
                    const int col0 = jb0 + m * 16 + q * 4;
                    {
                        float t0 = pow23(c[mm][0][0]), t1 = pow23(c[mm][0][1]);
                        float t2 = pow23(c[mm][1][0]), t3 = pow23(c[mm][1][1]);
                        float s = t0 + t1 + t2 + t3, p = s, o;
                        o = __shfl_up_sync(0xffffffffu, p, 1, 4); if (q >= 1) p += o;
                        o = __shfl_up_sync(0xffffffffu, p, 2, 4); if (q >= 2) p += o;
                        float tot = __shfl_sync(0xffffffffu, p, 3, 4);
                        float e = carry_lo + (p - s);
                        float o0 = e + t0, o1 = o0 + t1, o2 = o1 + t2, o3 = o2 + t3;
                        carry_lo += tot;
                        float4 st;
                        if (jt == diag)
                            st = make_float4(col0 >= gi_lo ? o0 : 0.f,
                                             col0 + 1 >= gi_lo ? o1 : 0.f,
                                             col0 + 2 >= gi_lo ? o2 : 0.f,
                                             col0 + 3 >= gi_lo ? o3 : 0.f);
                        else
                            st = make_float4(o0, o1, o2, o3);
                        stcs4(row_lo + col0, st);
                    }
                    {
                        float t0 = pow23(c[mm][0][2]), t1 = pow23(c[mm][0][3]);
                        float t2 = pow23(c[mm][1][2]), t3 = pow23(c[mm][1][3]);
                        float s = t0 + t1 + t2 + t3, p = s, o;
                        o = __shfl_up_sync(0xffffffffu, p, 1, 4); if (q >= 1) p += o;
                        o = __shfl_up_sync(0xffffffffu, p, 2, 4); if (q >= 2) p += o;
                        float tot = __shfl_sync(0xffffffffu, p, 3, 4);
                        float e = carry_hi + (p - s);
                        float o0 = e + t0, o1 = o0 + t1, o2 = o1 + t2, o3 = o2 + t3;
                        carry_hi += tot;
                        float4 st;
                        if (jt == diag)
                            st = make_float4(col0 >= gi_hi ? o0 : 0.f,
                                             col0 + 1 >= gi_hi ? o1 : 0.f,
                                             col0 + 2 >= gi_hi ? o2 : 0.f,
                                             col0 + 3 >= gi_hi ? o3 : 0.f);
                        else
                            st = make_float4(o0, o1, o2, o3);
                        stcs4(row_hi + col0, st);
                    }
                }
            }
        }

        if (nxt < NT) cp_wait0();
        __syncthreads();
    }
}

extern "C" void kernel_launch(void* const* d_in, const int* in_sizes, int n_in,
                              void* d_out, int out_size) {
    const float* k   = (const float*)d_in[0];
    const float* src = (const float*)d_in[1];
    const float* dst = (const float*)d_in[2];
    float*       out = (float*)d_out;

    cudaFuncSetAttribute(mha_hmma10_kernel,
                         cudaFuncAttributeMaxDynamicSharedMemorySize, SMEM_TOTAL);
    (void)in_sizes; (void)n_in; (void)out_size;

    prep_kernel<<<BHN * LEN * 4 / 256, 256>>>(k, src, dst);
    dim3 grid(LEN / 64, BHN);
    mha_hmma10_kernel<<<grid, 128, SMEM_TOTAL>>>(out);
}

// round 15
// speedup vs baseline: 1.1264x; 1.0695x over previous
#include <cuda_runtime.h>
#include <cuda_fp16.h>

#define ERRF 1e-12f
constexpr int LEN = 2048;
constexpr int DIM = 64;
constexpr int NT  = 16;
constexpr int BHN = 32;

// Prepacked fp16 operands, row-major [bh][row][64], 128B per row.
__device__ __half g_Ah[BHN * LEN * DIM];   // k*sqrt(src)  hi
__device__ __half g_Al[BHN * LEN * DIM];   // k*sqrt(src)  lo
__device__ __half g_Bh[BHN * LEN * DIM];   // k*sqrt(dest) fp16

// smem: A hi @0 (8K), A lo @8K, B double-buffer @16K (2 x 16K)
constexpr int OFF_ALO = 8192;
constexpr int OFF_B   = 16384;
constexpr int SMEM_TOTAL = 49152;   // 48 KB -> 4 CTAs/SM

#define SWZ(o) ((o) ^ (((o) >> 3) & 0x70))

__device__ __forceinline__ unsigned smem_u32(const void* p) {
    return (unsigned)__cvta_generic_to_shared(p);
}
__device__ __forceinline__ float fast_lg2(float x) { float y; asm("lg2.approx.f32 %0, %1;" : "=f"(y) : "f"(x)); return y; }
__device__ __forceinline__ float fast_ex2(float x) { float y; asm("ex2.approx.f32 %0, %1;" : "=f"(y) : "f"(x)); return y; }
__device__ __forceinline__ float pow23(float x) {
    return fast_ex2(fast_lg2(fmaxf(x, ERRF)) * 0.66666667f);
}

__device__ __forceinline__ void ldsm4(unsigned addr, unsigned& r0, unsigned& r1, unsigned& r2, unsigned& r3) {
    asm volatile("ldmatrix.sync.aligned.m8n8.x4.shared.b16 {%0,%1,%2,%3}, [%4];"
                 : "=r"(r0), "=r"(r1), "=r"(r2), "=r"(r3) : "r"(addr));
}

__device__ __forceinline__ void mma16816(float* c, const unsigned* a, unsigned b0, unsigned b1) {
    asm volatile("mma.sync.aligned.m16n8k16.row.col.f32.f16.f16.f32 "
                 "{%0,%1,%2,%3}, {%4,%5,%6,%7}, {%8,%9}, {%0,%1,%2,%3};"
                 : "+f"(c[0]), "+f"(c[1]), "+f"(c[2]), "+f"(c[3])
                 : "r"(a[0]), "r"(a[1]), "r"(a[2]), "r"(a[3]), "r"(b0), "r"(b1));
}
__device__ __forceinline__ void mma16816_z(float* c, const unsigned* a, unsigned b0, unsigned b1) {
    asm volatile("mma.sync.aligned.m16n8k16.row.col.f32.f16.f16.f32 "
                 "{%0,%1,%2,%3}, {%4,%5,%6,%7}, {%8,%9}, {%10,%10,%10,%10};"
                 : "=f"(c[0]), "=f"(c[1]), "=f"(c[2]), "=f"(c[3])
                 : "r"(a[0]), "r"(a[1]), "r"(a[2]), "r"(a[3]), "r"(b0), "r"(b1), "f"(0.f));
}

__device__ __forceinline__ void cp16(unsigned sdst, const void* gsrc) {
    asm volatile("cp.async.cg.shared.global [%0], [%1], 16;" :: "r"(sdst), "l"(gsrc) : "memory");
}
__device__ __forceinline__ void cp_commit() { asm volatile("cp.async.commit_group;" ::: "memory"); }
__device__ __forceinline__ void cp_wait0()  { asm volatile("cp.async.wait_group 0;" ::: "memory"); }

__device__ __forceinline__ void stcs4(float* p, float4 v) {
    asm volatile("st.global.cs.v4.f32 [%0], {%1,%2,%3,%4};"
                 :: "l"(p), "f"(v.x), "f"(v.y), "f"(v.z), "f"(v.w) : "memory");
}
__device__ __forceinline__ void stcs4_zero(float* p) {
    asm volatile("st.global.cs.v4.f32 [%0], {%1, %1, %1, %1};" :: "l"(p), "f"(0.f) : "memory");
}

// ---------------- prep kernel: fp32 -> scaled fp16 hi/lo ----------------
__global__ void __launch_bounds__(256)
prep_kernel(const float* __restrict__ k, const float* __restrict__ src,
            const float* __restrict__ dst)
{
    const int idx = blockIdx.x * 256 + threadIdx.x;
    const int row = idx >> 2;
    const int q   = idx & 3;
    const float ws = sqrtf(src[row] + ERRF);
    const float wd = sqrtf(dst[row] + ERRF);
    const float4* kp = reinterpret_cast<const float4*>(k + (size_t)row * DIM + q * 16);

    __half2 oh[8], ol[8], ob[8];
    #pragma unroll
    for (int p = 0; p < 4; ++p) {
        float4 v = kp[p];
        float a0 = v.x * ws, a1 = v.y * ws, a2 = v.z * ws, a3 = v.w * ws;
        __half h0 = __float2half_rn(a0), h1 = __float2half_rn(a1);
        __half h2 = __float2half_rn(a2), h3 = __float2half_rn(a3);
        oh[p * 2]     = __half2(h0, h1);
        oh[p * 2 + 1] = __half2(h2, h3);
        ol[p * 2]     = __floats2half2_rn(a0 - __half2float(h0), a1 - __half2float(h1));
        ol[p * 2 + 1] = __floats2half2_rn(a2 - __half2float(h2), a3 - __half2float(h3));
        ob[p * 2]     = __floats2half2_rn(v.x * wd, v.y * wd);
        ob[p * 2 + 1] = __floats2half2_rn(v.z * wd, v.w * wd);
    }
    const size_t o = (size_t)row * DIM + q * 16;
    uint4* dAh = reinterpret_cast<uint4*>(g_Ah + o);
    uint4* dAl = reinterpret_cast<uint4*>(g_Al + o);
    uint4* dBh = reinterpret_cast<uint4*>(g_Bh + o);
    const uint4* sh = reinterpret_cast<const uint4*>(oh);
    const uint4* sl = reinterpret_cast<const uint4*>(ol);
    const uint4* sb = reinterpret_cast<const uint4*>(ob);
    dAh[0] = sh[0]; dAh[1] = sh[1];
    dAl[0] = sl[0]; dAl[1] = sl[1];
    dBh[0] = sb[0]; dBh[1] = sb[1];
}

// B tile copy with column-coalescing row permutation:
// within each 16-row group, true row t -> position [0,1,8,9,2,3,10,11,4,5,12,13,6,7,14,15]
__device__ __forceinline__ void cp_tile16_perm(const char* gsrc, unsigned sdst, int tid) {
    #pragma unroll
    for (int i = 0; i < 8; ++i) {
        int cid = tid + 128 * i;
        int row = cid >> 3;
        int pr  = (row & ~15) | ((row & 2) << 2) | ((row >> 1) & 6) | (row & 1);
        unsigned dst = (unsigned)(pr * 128 + (cid & 7) * 16);
        cp16(sdst + SWZ(dst), gsrc + (unsigned)(cid << 4));
    }
}
// A tile (8KB, 64 rows), no permutation
__device__ __forceinline__ void cp_tile8(const char* gsrc, unsigned sdst, int tid) {
    #pragma unroll
    for (int i = 0; i < 4; ++i) {
        int cid = tid + 128 * i;
        unsigned off = (unsigned)(cid << 4);
        cp16(sdst + SWZ(off), gsrc + off);
    }
}

// ---------------- main kernel: 128 threads, 64-row i-tile, 4 CTAs/SM ----------------
__global__ void __launch_bounds__(128, 4)
mha_hmma11_kernel(float* __restrict__ out)
{
    extern __shared__ char smem[];
    const int tid = threadIdx.x;
    const int wid = tid >> 5;
    const int lid = tid & 31;
    const int bh  = blockIdx.y;
    const int diag = blockIdx.x >> 1;
    const int it0 = blockIdx.x * 64;

    float* ob = out + (size_t)bh * LEN * LEN;
    const char* gA  = reinterpret_cast<const char*>(g_Ah + ((size_t)bh * LEN + it0) * DIM);
    const char* gAl = reinterpret_cast<const char*>(g_Al + ((size_t)bh * LEN + it0) * DIM);
    const char* gB  = reinterpret_cast<const char*>(g_Bh + (size_t)bh * LEN * DIM);

    const unsigned sbase = smem_u32(smem);

    cp_tile8(gA,  sbase, tid);
    cp_tile8(gAl, sbase + OFF_ALO, tid);
    cp_tile16_perm(gB, sbase + OFF_B, tid);
    cp_commit();
    cp_wait0();
    __syncthreads();

    // ldmatrix lane addressing
    const int l7  = lid & 7;
    const int sel = lid >> 3;
    const unsigned xk = (unsigned)(l7 << 4);
    const int arow  = wid * 16 + l7 + ((sel & 1) ? 8 : 0);
    const unsigned akoff = (sel & 2) ? 16u : 0u;
    const int bn    = l7 + ((sel & 2) ? 8 : 0);
    const unsigned bkoff = (sel & 1) ? 16u : 0u;
    const unsigned a_lane = sbase + (unsigned)(arow * 128);
    const unsigned b_lane = sbase + OFF_B + (unsigned)(bn * 128);

    // A fragments register-resident
    unsigned ah[4][4], al[4][4];
    #pragma unroll
    for (int ks = 0; ks < 4; ++ks) {
        const unsigned ak = ((unsigned)(ks * 32) + akoff) ^ xk;
        ldsm4(a_lane + ak, ah[ks][0], ah[ks][1], ah[ks][2], ah[ks][3]);
        ldsm4(a_lane + OFF_ALO + ak, al[ks][0], al[ks][1], al[ks][2], al[ks][3]);
    }

    // epilogue lane mapping: for fragment pair (2m,2m+1), lane q owns TRUE cols 16m+4q..+3
    const int q  = lid & 3;
    const int g4 = lid >> 2;
    const int gi_lo = it0 + wid * 16 + g4;
    const int gi_hi = gi_lo + 8;
    float* const row_lo = ob + (size_t)gi_lo * LEN;
    float* const row_hi = ob + (size_t)gi_hi * LEN;

    float carry_lo = 0.f, carry_hi = 0.f;
    float part_lo = 0.f,  part_hi = 0.f;

    for (int jt = 0; jt < NT; ++jt) {
        const int jb0 = jt * 128;
        const bool below = (jt < diag);
        const int nxt = jt + 1;

        if (nxt < NT) {
            cp_tile16_perm(gB + (size_t)nxt * 16384, sbase + OFF_B + (nxt & 1) * 16384, tid);
            cp_commit();
        }

        // zero-fill stores for fully-masked tiles (streaming, row-contiguous)
        if (below) {
            float* base = ob + (size_t)(it0 + wid * 16) * LEN + jb0 + lid * 4;
            #pragma unroll
            for (int r = 0; r < 16; ++r)
                stcs4_zero(base + (size_t)r * LEN);
        }

        float c[16][4];
        const unsigned bbuf = (unsigned)((jt & 1) * 16384);
        if (below) {
            #pragma unroll
            for (int ks = 0; ks < 4; ++ks) {
                const unsigned bkb = ((unsigned)(ks * 32) + bkoff) ^ xk;
                #pragma unroll
                for (int np = 0; np < 8; ++np) {
                    unsigned b0, b1, b2, b3;
                    ldsm4(b_lane + bbuf + (unsigned)(np * 2048) + bkb, b0, b1, b2, b3);
                    if (ks == 0) {
                        mma16816_z(c[np * 2],     ah[0], b0, b1);
                        mma16816_z(c[np * 2 + 1], ah[0], b2, b3);
                    } else {
                        mma16816(c[np * 2],     ah[ks], b0, b1);
                        mma16816(c[np * 2 + 1], ah[ks], b2, b3);
                    }
                }
            }
        } else {
            #pragma unroll
            for (int ks = 0; ks < 4; ++ks) {
                const unsigned bkb = ((unsigned)(ks * 32) + bkoff) ^ xk;
                #pragma unroll
                for (int np = 0; np < 8; ++np) {
                    unsigned b0, b1, b2, b3;
                    ldsm4(b_lane + bbuf + (unsigned)(np * 2048) + bkb, b0, b1, b2, b3);
                    if (ks == 0) {
                        mma16816_z(c[np * 2],     ah[0], b0, b1);
                        mma16816_z(c[np * 2 + 1], ah[0], b2, b3);
                    } else {
                        mma16816(c[np * 2],     ah[ks], b0, b1);
                        mma16816(c[np * 2 + 1], ah[ks], b2, b3);
                    }
                    mma16816(c[np * 2],     al[ks], b0, b1);
                    mma16816(c[np * 2 + 1], al[ks], b2, b3);
                }
            }
        }

        // lane-partials -> full-row carry at the diagonal tile
        if (jt == diag) {
            float v = part_lo;
            v += __shfl_xor_sync(0xffffffffu, v, 1, 4);
            v += __shfl_xor_sync(0xffffffffu, v, 2, 4);
            carry_lo = v;
            v = part_hi;
            v += __shfl_xor_sync(0xffffffffu, v, 1, 4);
            v += __shfl_xor_sync(0xffffffffu, v, 2, 4);
            carry_hi = v;
        }

        // ---- batched epilogue: stage A = independent scans (in-place local prefixes
        //      + tot regs), stage B = short FADD carry chain + stores ----
        auto epi_group = [&](int g, bool masked) {
            float totl[4], toth[4];
            // stage A: lo half, 4 independent pair-scans
            #pragma unroll
            for (int mm = 0; mm < 4; ++mm) {
                const int m = g * 4 + mm;
                float t0 = pow23(c[2 * m][0]), t1 = pow23(c[2 * m][1]);
                float t2 = pow23(c[2 * m + 1][0]), t3 = pow23(c[2 * m + 1][1]);
                float s = t0 + t1 + t2 + t3, p = s, o;
                o = __shfl_up_sync(0xffffffffu, p, 1, 4); if (q >= 1) p += o;
                o = __shfl_up_sync(0xffffffffu, p, 2, 4); if (q >= 2) p += o;
                totl[mm] = __shfl_sync(0xffffffffu, p, 3, 4);
                float e = p - s;
                float w0 = e + t0, w1 = w0 + t1, w2 = w1 + t2, w3 = w2 + t3;
                c[2 * m][0] = w0; c[2 * m][1] = w1;
                c[2 * m + 1][0] = w2; c[2 * m + 1][1] = w3;
            }
            // stage B: lo half, serial carry chain (4 FADDs) + stores
            #pragma unroll
            for (int mm = 0; mm < 4; ++mm) {
                const int m = g * 4 + mm;
                const int col0 = jb0 + m * 16 + q * 4;
                float o0 = carry_lo + c[2 * m][0];
                float o1 = carry_lo + c[2 * m][1];
                float o2 = carry_lo + c[2 * m + 1][0];
                float o3 = carry_lo + c[2 * m + 1][1];
                carry_lo += totl[mm];
                float4 st = masked ? make_float4(col0 >= gi_lo ? o0 : 0.f,
                                                 col0 + 1 >= gi_lo ? o1 : 0.f,
                                                 col0 + 2 >= gi_lo ? o2 : 0.f,
                                                 col0 + 3 >= gi_lo ? o3 : 0.f)
                                   : make_float4(o0, o1, o2, o3);
                stcs4(row_lo + col0, st);
            }
            // stage A: hi half
            #pragma unroll
            for (int mm = 0; mm < 4; ++mm) {
                const int m = g * 4 + mm;
                float t0 = pow23(c[2 * m][2]), t1 = pow23(c[2 * m][3]);
                float t2 = pow23(c[2 * m + 1][2]), t3 = pow23(c[2 * m + 1][3]);
                float s = t0 + t1 + t2 + t3, p = s, o;
                o = __shfl_up_sync(0xffffffffu, p, 1, 4); if (q >= 1) p += o;
                o = __shfl_up_sync(0xffffffffu, p, 2, 4); if (q >= 2) p += o;
                toth[mm] = __shfl_sync(0xffffffffu, p, 3, 4);
                float e = p - s;
                float w0 = e + t0, w1 = w0 + t1, w2 = w1 + t2, w3 = w2 + t3;
                c[2 * m][2] = w0; c[2 * m][3] = w1;
                c[2 * m + 1][2] = w2; c[2 * m + 1][3] = w3;
            }
            // stage B: hi half
            #pragma unroll
            for (int mm = 0; mm < 4; ++mm) {
                const int m = g * 4 + mm;
                const int col0 = jb0 + m * 16 + q * 4;
                float o0 = carry_hi + c[2 * m][2];
                float o1 = carry_hi + c[2 * m][3];
                float o2 = carry_hi + c[2 * m + 1][2];
                float o3 = carry_hi + c[2 * m + 1][3];
                carry_hi += toth[mm];
                float4 st = masked ? make_float4(col0 >= gi_hi ? o0 : 0.f,
                                                 col0 + 1 >= gi_hi ? o1 : 0.f,
                                                 col0 + 2 >= gi_hi ? o2 : 0.f,
                                                 col0 + 3 >= gi_hi ? o3 : 0.f)
                                   : make_float4(o0, o1, o2, o3);
                stcs4(row_hi + col0, st);
            }
        };

        auto accum_only = [&](int nb) {
            part_lo += pow23(c[nb][0]) + pow23(c[nb][1]);
            part_hi += pow23(c[nb][2]) + pow23(c[nb][3]);
        };

        if (below) {
            #pragma unroll
            for (int nb = 0; nb < 16; ++nb) accum_only(nb);
        } else if (jt == diag) {
            epi_group(0, true);
            epi_group(1, true);
        } else {
            epi_group(0, false);
            epi_group(1, false);
        }

        if (nxt < NT) cp_wait0();
        __syncthreads();
    }
}

extern "C" void kernel_launch(void* const* d_in, const int* in_sizes, int n_in,
                              void* d_out, int out_size) {
    const float* k   = (const float*)d_in[0];
    const float* src = (const float*)d_in[1];
    const float* dst = (const float*)d_in[2];
    float*       out = (float*)d_out;

    cudaFuncSetAttribute(mha_hmma11_kernel,
                         cudaFuncAttributeMaxDynamicSharedMemorySize, SMEM_TOTAL);
    (void)in_sizes; (void)n_in; (void)out_size;

    prep_kernel<<<BHN * LEN * 4 / 256, 256>>>(k, src, dst);
    dim3 grid(LEN / 64, BHN);
    mha_hmma11_kernel<<<grid, 128, SMEM_TOTAL>>>(out);
}

// round 16
// speedup vs baseline: 1.1271x; 1.0007x over previous
#include <cuda_runtime.h>
#include <cuda_fp16.h>

#define ERRF 1e-12f
constexpr int LEN = 2048;
constexpr int DIM = 64;
constexpr int NT  = 16;
constexpr int BHN = 32;

// Prepacked fp16 operands, row-major [bh][row][64], 128B per row.
__device__ __half g_Ah[BHN * LEN * DIM];   // k*sqrt(src)  hi
__device__ __half g_Al[BHN * LEN * DIM];   // k*sqrt(src)  lo
__device__ __half g_Bh[BHN * LEN * DIM];   // k*sqrt(dest) fp16

// smem: A hi @0 (8K), A lo @8K, B double-buffer @16K (2 x 16K)
constexpr int OFF_ALO = 8192;
constexpr int OFF_B   = 16384;
constexpr int SMEM_TOTAL = 49152;   // 48 KB -> 4 CTAs/SM

#define SWZ(o) ((o) ^ (((o) >> 3) & 0x70))

__device__ __forceinline__ unsigned smem_u32(const void* p) {
    return (unsigned)__cvta_generic_to_shared(p);
}
__device__ __forceinline__ float fast_lg2(float x) { float y; asm("lg2.approx.f32 %0, %1;" : "=f"(y) : "f"(x)); return y; }
__device__ __forceinline__ float fast_ex2(float x) { float y; asm("ex2.approx.f32 %0, %1;" : "=f"(y) : "f"(x)); return y; }
__device__ __forceinline__ float pow23(float x) {
    return fast_ex2(fast_lg2(fmaxf(x, ERRF)) * 0.66666667f);
}

__device__ __forceinline__ void ldsm4(unsigned addr, unsigned& r0, unsigned& r1, unsigned& r2, unsigned& r3) {
    asm volatile("ldmatrix.sync.aligned.m8n8.x4.shared.b16 {%0,%1,%2,%3}, [%4];"
                 : "=r"(r0), "=r"(r1), "=r"(r2), "=r"(r3) : "r"(addr));
}

__device__ __forceinline__ void mma16816(float* c, const unsigned* a, unsigned b0, unsigned b1) {
    asm volatile("mma.sync.aligned.m16n8k16.row.col.f32.f16.f16.f32 "
                 "{%0,%1,%2,%3}, {%4,%5,%6,%7}, {%8,%9}, {%0,%1,%2,%3};"
                 : "+f"(c[0]), "+f"(c[1]), "+f"(c[2]), "+f"(c[3])
                 : "r"(a[0]), "r"(a[1]), "r"(a[2]), "r"(a[3]), "r"(b0), "r"(b1));
}
__device__ __forceinline__ void mma16816_z(float* c, const unsigned* a, unsigned b0, unsigned b1) {
    asm volatile("mma.sync.aligned.m16n8k16.row.col.f32.f16.f16.f32 "
                 "{%0,%1,%2,%3}, {%4,%5,%6,%7}, {%8,%9}, {%10,%10,%10,%10};"
                 : "=f"(c[0]), "=f"(c[1]), "=f"(c[2]), "=f"(c[3])
                 : "r"(a[0]), "r"(a[1]), "r"(a[2]), "r"(a[3]), "r"(b0), "r"(b1), "f"(0.f));
}

__device__ __forceinline__ void cp16(unsigned sdst, const void* gsrc) {
    asm volatile("cp.async.cg.shared.global [%0], [%1], 16;" :: "r"(sdst), "l"(gsrc) : "memory");
}
__device__ __forceinline__ void cp_commit() { asm volatile("cp.async.commit_group;" ::: "memory"); }
__device__ __forceinline__ void cp_wait0()  { asm volatile("cp.async.wait_group 0;" ::: "memory"); }

__device__ __forceinline__ void stcs4(float* p, float4 v) {
    asm volatile("st.global.cs.v4.f32 [%0], {%1,%2,%3,%4};"
                 :: "l"(p), "f"(v.x), "f"(v.y), "f"(v.z), "f"(v.w) : "memory");
}
__device__ __forceinline__ void stcs4_zero(float* p) {
    asm volatile("st.global.cs.v4.f32 [%0], {%1, %1, %1, %1};" :: "l"(p), "f"(0.f) : "memory");
}

// ---------------- prep kernel: fp32 -> scaled fp16 hi/lo ----------------
__global__ void __launch_bounds__(256)
prep_kernel(const float* __restrict__ k, const float* __restrict__ src,
            const float* __restrict__ dst)
{
    const int idx = blockIdx.x * 256 + threadIdx.x;
    const int row = idx >> 2;
    const int q   = idx & 3;
    const float ws = sqrtf(src[row] + ERRF);
    const float wd = sqrtf(dst[row] + ERRF);
    const float4* kp = reinterpret_cast<const float4*>(k + (size_t)row * DIM + q * 16);

    __half2 oh[8], ol[8], ob[8];
    #pragma unroll
    for (int p = 0; p < 4; ++p) {
        float4 v = kp[p];
        float a0 = v.x * ws, a1 = v.y * ws, a2 = v.z * ws, a3 = v.w * ws;
        __half h0 = __float2half_rn(a0), h1 = __float2half_rn(a1);
        __half h2 = __float2half_rn(a2), h3 = __float2half_rn(a3);
        oh[p * 2]     = __half2(h0, h1);
        oh[p * 2 + 1] = __half2(h2, h3);
        ol[p * 2]     = __floats2half2_rn(a0 - __half2float(h0), a1 - __half2float(h1));
        ol[p * 2 + 1] = __floats2half2_rn(a2 - __half2float(h2), a3 - __half2float(h3));
        ob[p * 2]     = __floats2half2_rn(v.x * wd, v.y * wd);
        ob[p * 2 + 1] = __floats2half2_rn(v.z * wd, v.w * wd);
    }
    const size_t o = (size_t)row * DIM + q * 16;
    uint4* dAh = reinterpret_cast<uint4*>(g_Ah + o);
    uint4* dAl = reinterpret_cast<uint4*>(g_Al + o);
    uint4* dBh = reinterpret_cast<uint4*>(g_Bh + o);
    const uint4* sh = reinterpret_cast<const uint4*>(oh);
    const uint4* sl = reinterpret_cast<const uint4*>(ol);
    const uint4* sb = reinterpret_cast<const uint4*>(ob);
    dAh[0] = sh[0]; dAh[1] = sh[1];
    dAl[0] = sl[0]; dAl[1] = sl[1];
    dBh[0] = sb[0]; dBh[1] = sb[1];
}

// B tile copy with column-coalescing row permutation:
// within each 16-row group, true row t -> position [0,1,8,9,2,3,10,11,4,5,12,13,6,7,14,15]
__device__ __forceinline__ void cp_tile16_perm(const char* gsrc, unsigned sdst, int tid) {
    #pragma unroll
    for (int i = 0; i < 8; ++i) {
        int cid = tid + 128 * i;
        int row = cid >> 3;
        int pr  = (row & ~15) | ((row & 2) << 2) | ((row >> 1) & 6) | (row & 1);
        unsigned dst = (unsigned)(pr * 128 + (cid & 7) * 16);
        cp16(sdst + SWZ(dst), gsrc + (unsigned)(cid << 4));
    }
}
// A tile (8KB, 64 rows), no permutation
__device__ __forceinline__ void cp_tile8(const char* gsrc, unsigned sdst, int tid) {
    #pragma unroll
    for (int i = 0; i < 4; ++i) {
        int cid = tid + 128 * i;
        unsigned off = (unsigned)(cid << 4);
        cp16(sdst + SWZ(off), gsrc + off);
    }
}

// ---------------- main kernel: 128 threads, 64-row i-tile, 4 CTAs/SM ----------------
__global__ void __launch_bounds__(128, 4)
mha_hmma11_kernel(float* __restrict__ out)
{
    extern __shared__ char smem[];
    const int tid = threadIdx.x;
    const int wid = tid >> 5;
    const int lid = tid & 31;
    const int bh  = blockIdx.y;
    const int diag = blockIdx.x >> 1;
    const int it0 = blockIdx.x * 64;

    float* ob = out + (size_t)bh * LEN * LEN;
    const char* gA  = reinterpret_cast<const char*>(g_Ah + ((size_t)bh * LEN + it0) * DIM);
    const char* gAl = reinterpret_cast<const char*>(g_Al + ((size_t)bh * LEN + it0) * DIM);
    const char* gB  = reinterpret_cast<const char*>(g_Bh + (size_t)bh * LEN * DIM);

    const unsigned sbase = smem_u32(smem);

    cp_tile8(gA,  sbase, tid);
    cp_tile8(gAl, sbase + OFF_ALO, tid);
    cp_tile16_perm(gB, sbase + OFF_B, tid);
    cp_commit();
    cp_wait0();
    __syncthreads();

    // ldmatrix lane addressing
    const int l7  = lid & 7;
    const int sel = lid >> 3;
    const unsigned xk = (unsigned)(l7 << 4);
    const int arow  = wid * 16 + l7 + ((sel & 1) ? 8 : 0);
    const unsigned akoff = (sel & 2) ? 16u : 0u;
    const int bn    = l7 + ((sel & 2) ? 8 : 0);
    const unsigned bkoff = (sel & 1) ? 16u : 0u;
    const unsigned a_lane = sbase + (unsigned)(arow * 128);
    const unsigned b_lane = sbase + OFF_B + (unsigned)(bn * 128);

    // A fragments register-resident
    unsigned ah[4][4], al[4][4];
    #pragma unroll
    for (int ks = 0; ks < 4; ++ks) {
        const unsigned ak = ((unsigned)(ks * 32) + akoff) ^ xk;
        ldsm4(a_lane + ak, ah[ks][0], ah[ks][1], ah[ks][2], ah[ks][3]);
        ldsm4(a_lane + OFF_ALO + ak, al[ks][0], al[ks][1], al[ks][2], al[ks][3]);
    }

    // epilogue lane mapping: for fragment pair (2m,2m+1), lane q owns TRUE cols 16m+4q..+3
    const int q  = lid & 3;
    const int g4 = lid >> 2;
    const int gi_lo = it0 + wid * 16 + g4;
    const int gi_hi = gi_lo + 8;
    float* const row_lo = ob + (size_t)gi_lo * LEN;
    float* const row_hi = ob + (size_t)gi_hi * LEN;

    float carry_lo = 0.f, carry_hi = 0.f;
    float part_lo = 0.f,  part_hi = 0.f;

    for (int jt = 0; jt < NT; ++jt) {
        const int jb0 = jt * 128;
        const bool below = (jt < diag);
        const int nxt = jt + 1;

        if (nxt < NT) {
            cp_tile16_perm(gB + (size_t)nxt * 16384, sbase + OFF_B + (nxt & 1) * 16384, tid);
            cp_commit();
        }

        // zero-fill stores for fully-masked tiles (streaming, row-contiguous)
        if (below) {
            float* base = ob + (size_t)(it0 + wid * 16) * LEN + jb0 + lid * 4;
            #pragma unroll
            for (int r = 0; r < 16; ++r)
                stcs4_zero(base + (size_t)r * LEN);
        }

        float c[16][4];
        const unsigned bbuf = (unsigned)((jt & 1) * 16384);
        if (below) {
            #pragma unroll
            for (int ks = 0; ks < 4; ++ks) {
                const unsigned bkb = ((unsigned)(ks * 32) + bkoff) ^ xk;
                #pragma unroll
                for (int np = 0; np < 8; ++np) {
                    unsigned b0, b1, b2, b3;
                    ldsm4(b_lane + bbuf + (unsigned)(np * 2048) + bkb, b0, b1, b2, b3);
                    if (ks == 0) {
                        mma16816_z(c[np * 2],     ah[0], b0, b1);
                        mma16816_z(c[np * 2 + 1], ah[0], b2, b3);
                    } else {
                        mma16816(c[np * 2],     ah[ks], b0, b1);
                        mma16816(c[np * 2 + 1], ah[ks], b2, b3);
                    }
                }
            }
        } else {
            #pragma unroll
            for (int ks = 0; ks < 4; ++ks) {
                const unsigned bkb = ((unsigned)(ks * 32) + bkoff) ^ xk;
                #pragma unroll
                for (int np = 0; np < 8; ++np) {
                    unsigned b0, b1, b2, b3;
                    ldsm4(b_lane + bbuf + (unsigned)(np * 2048) + bkb, b0, b1, b2, b3);
                    if (ks == 0) {
                        mma16816_z(c[np * 2],     ah[0], b0, b1);
                        mma16816_z(c[np * 2 + 1], ah[0], b2, b3);
                    } else {
                        mma16816(c[np * 2],     ah[ks], b0, b1);
                        mma16816(c[np * 2 + 1], ah[ks], b2, b3);
                    }
                    mma16816(c[np * 2],     al[ks], b0, b1);
                    mma16816(c[np * 2 + 1], al[ks], b2, b3);
                }
            }
        }

        // lane-partials -> full-row carry at the diagonal tile
        if (jt == diag) {
            float v = part_lo;
            v += __shfl_xor_sync(0xffffffffu, v, 1, 4);
            v += __shfl_xor_sync(0xffffffffu, v, 2, 4);
            carry_lo = v;
            v = part_hi;
            v += __shfl_xor_sync(0xffffffffu, v, 1, 4);
            v += __shfl_xor_sync(0xffffffffu, v, 2, 4);
            carry_hi = v;
        }

        // ---- batched epilogue: stage A = independent scans (in-place local prefixes
        //      + tot regs), stage B = short FADD carry chain + stores ----
        auto epi_group = [&](int g, bool masked) {
            float totl[4], toth[4];
            // stage A: lo half, 4 independent pair-scans
            #pragma unroll
            for (int mm = 0; mm < 4; ++mm) {
                const int m = g * 4 + mm;
                float t0 = pow23(c[2 * m][0]), t1 = pow23(c[2 * m][1]);
                float t2 = pow23(c[2 * m + 1][0]), t3 = pow23(c[2 * m + 1][1]);
                float s = t0 + t1 + t2 + t3, p = s, o;
                o = __shfl_up_sync(0xffffffffu, p, 1, 4); if (q >= 1) p += o;
                o = __shfl_up_sync(0xffffffffu, p, 2, 4); if (q >= 2) p += o;
                totl[mm] = __shfl_sync(0xffffffffu, p, 3, 4);
                float e = p - s;
                float w0 = e + t0, w1 = w0 + t1, w2 = w1 + t2, w3 = w2 + t3;
                c[2 * m][0] = w0; c[2 * m][1] = w1;
                c[2 * m + 1][0] = w2; c[2 * m + 1][1] = w3;
            }
            // stage B: lo half, serial carry chain (4 FADDs) + stores
            #pragma unroll
            for (int mm = 0; mm < 4; ++mm) {
                const int m = g * 4 + mm;
                const int col0 = jb0 + m * 16 + q * 4;
                float o0 = carry_lo + c[2 * m][0];
                float o1 = carry_lo + c[2 * m][1];
                float o2 = carry_lo + c[2 * m + 1][0];
                float o3 = carry_lo + c[2 * m + 1][1];
                carry_lo += totl[mm];
                float4 st = masked ? make_float4(col0 >= gi_lo ? o0 : 0.f,
                                                 col0 + 1 >= gi_lo ? o1 : 0.f,
                                                 col0 + 2 >= gi_lo ? o2 : 0.f,
                                                 col0 + 3 >= gi_lo ? o3 : 0.f)
                                   : make_float4(o0, o1, o2, o3);
                stcs4(row_lo + col0, st);
            }
            // stage A: hi half
            #pragma unroll
            for (int mm = 0; mm < 4; ++mm) {
                const int m = g * 4 + mm;
                float t0 = pow23(c[2 * m][2]), t1 = pow23(c[2 * m][3]);
                float t2 = pow23(c[2 * m + 1][2]), t3 = pow23(c[2 * m + 1][3]);
                float s = t0 + t1 + t2 + t3, p = s, o;
                o = __shfl_up_sync(0xffffffffu, p, 1, 4); if (q >= 1) p += o;
                o = __shfl_up_sync(0xffffffffu, p, 2, 4); if (q >= 2) p += o;
                toth[mm] = __shfl_sync(0xffffffffu, p, 3, 4);
                float e = p - s;
                float w0 = e + t0, w1 = w0 + t1, w2 = w1 + t2, w3 = w2 + t3;
                c[2 * m][2] = w0; c[2 * m][3] = w1;
                c[2 * m + 1][2] = w2; c[2 * m + 1][3] = w3;
            }
            // stage B: hi half
            #pragma unroll
            for (int mm = 0; mm < 4; ++mm) {
                const int m = g * 4 + mm;
                const int col0 = jb0 + m * 16 + q * 4;
                float o0 = carry_hi + c[2 * m][2];
                float o1 = carry_hi + c[2 * m][3];
                float o2 = carry_hi + c[2 * m + 1][2];
                float o3 = carry_hi + c[2 * m + 1][3];
                carry_hi += toth[mm];
                float4 st = masked ? make_float4(col0 >= gi_hi ? o0 : 0.f,
                                                 col0 + 1 >= gi_hi ? o1 : 0.f,
                                                 col0 + 2 >= gi_hi ? o2 : 0.f,
                                                 col0 + 3 >= gi_hi ? o3 : 0.f)
                                   : make_float4(o0, o1, o2, o3);
                stcs4(row_hi + col0, st);
            }
        };

        auto accum_only = [&](int nb) {
            part_lo += pow23(c[nb][0]) + pow23(c[nb][1]);
            part_hi += pow23(c[nb][2]) + pow23(c[nb][3]);
        };

        if (below) {
            #pragma unroll
            for (int nb = 0; nb < 16; ++nb) accum_only(nb);
        } else if (jt == diag) {
            epi_group(0, true);
            epi_group(1, true);
        } else {
            epi_group(0, false);
            epi_group(1, false);
        }

        if (nxt < NT) cp_wait0();
        __syncthreads();
    }
}

extern "C" void kernel_launch(void* const* d_in, const int* in_sizes, int n_in,
                              void* d_out, int out_size) {
    const float* k   = (const float*)d_in[0];
    const float* src = (const float*)d_in[1];
    const float* dst = (const float*)d_in[2];
    float*       out = (float*)d_out;

    cudaFuncSetAttribute(mha_hmma11_kernel,
                         cudaFuncAttributeMaxDynamicSharedMemorySize, SMEM_TOTAL);
    (void)in_sizes; (void)n_in; (void)out_size;

    prep_kernel<<<BHN * LEN * 4 / 256, 256>>>(k, src, dst);
    dim3 grid(LEN / 64, BHN);
    mha_hmma11_kernel<<<grid, 128, SMEM_TOTAL>>>(out);
}

// round 17
// speedup vs baseline: 1.1606x; 1.0297x over previous
#include <cuda_runtime.h>
#include <cuda_fp16.h>

#define ERRF 1e-12f
constexpr int LEN = 2048;
constexpr int DIM = 64;
constexpr int NT  = 16;
constexpr int BHN = 32;

// Prepacked fp16 operands, row-major [bh][row][64], 128B per row.
__device__ __half g_Ah[BHN * LEN * DIM];   // k*sqrt(src)  hi
__device__ __half g_Al[BHN * LEN * DIM];   // k*sqrt(src)  lo
__device__ __half g_Bh[BHN * LEN * DIM];   // k*sqrt(dest) fp16

// smem: A hi @0 (8K), A lo @8K, B double-buffer @16K (2 x 16K)
constexpr int OFF_ALO = 8192;
constexpr int OFF_B   = 16384;
constexpr int SMEM_TOTAL = 49152;   // 48 KB -> 4 CTAs/SM

#define SWZ(o) ((o) ^ (((o) >> 3) & 0x70))

__device__ __forceinline__ unsigned smem_u32(const void* p) {
    return (unsigned)__cvta_generic_to_shared(p);
}
__device__ __forceinline__ float fast_lg2(float x) { float y; asm("lg2.approx.f32 %0, %1;" : "=f"(y) : "f"(x)); return y; }
__device__ __forceinline__ float fast_ex2(float x) { float y; asm("ex2.approx.f32 %0, %1;" : "=f"(y) : "f"(x)); return y; }
__device__ __forceinline__ float pow23(float x) {
    return fast_ex2(fast_lg2(fmaxf(x, ERRF)) * 0.66666667f);
}

__device__ __forceinline__ void ldsm4(unsigned addr, unsigned& r0, unsigned& r1, unsigned& r2, unsigned& r3) {
    asm volatile("ldmatrix.sync.aligned.m8n8.x4.shared.b16 {%0,%1,%2,%3}, [%4];"
                 : "=r"(r0), "=r"(r1), "=r"(r2), "=r"(r3) : "r"(addr));
}

__device__ __forceinline__ void mma16816(float* c, const unsigned* a, unsigned b0, unsigned b1) {
    asm volatile("mma.sync.aligned.m16n8k16.row.col.f32.f16.f16.f32 "
                 "{%0,%1,%2,%3}, {%4,%5,%6,%7}, {%8,%9}, {%0,%1,%2,%3};"
                 : "+f"(c[0]), "+f"(c[1]), "+f"(c[2]), "+f"(c[3])
                 : "r"(a[0]), "r"(a[1]), "r"(a[2]), "r"(a[3]), "r"(b0), "r"(b1));
}
__device__ __forceinline__ void mma16816_z(float* c, const unsigned* a, unsigned b0, unsigned b1) {
    asm volatile("mma.sync.aligned.m16n8k16.row.col.f32.f16.f16.f32 "
                 "{%0,%1,%2,%3}, {%4,%5,%6,%7}, {%8,%9}, {%10,%10,%10,%10};"
                 : "=f"(c[0]), "=f"(c[1]), "=f"(c[2]), "=f"(c[3])
                 : "r"(a[0]), "r"(a[1]), "r"(a[2]), "r"(a[3]), "r"(b0), "r"(b1), "f"(0.f));
}

__device__ __forceinline__ void cp16(unsigned sdst, const void* gsrc) {
    asm volatile("cp.async.cg.shared.global [%0], [%1], 16;" :: "r"(sdst), "l"(gsrc) : "memory");
}
__device__ __forceinline__ void cp_commit() { asm volatile("cp.async.commit_group;" ::: "memory"); }
__device__ __forceinline__ void cp_wait0()  { asm volatile("cp.async.wait_group 0;" ::: "memory"); }

__device__ __forceinline__ void stcs4(float* p, float4 v) {
    asm volatile("st.global.cs.v4.f32 [%0], {%1,%2,%3,%4};"
                 :: "l"(p), "f"(v.x), "f"(v.y), "f"(v.z), "f"(v.w) : "memory");
}
__device__ __forceinline__ void stcs4_zero(float* p) {
    asm volatile("st.global.cs.v4.f32 [%0], {%1, %1, %1, %1};" :: "l"(p), "f"(0.f) : "memory");
}

// ---------------- prep kernel: fp32 -> scaled fp16 hi/lo ----------------
__global__ void __launch_bounds__(256)
prep_kernel(const float* __restrict__ k, const float* __restrict__ src,
            const float* __restrict__ dst)
{
    const int idx = blockIdx.x * 256 + threadIdx.x;
    const int row = idx >> 2;
    const int q   = idx & 3;
    const float ws = sqrtf(src[row] + ERRF);
    const float wd = sqrtf(dst[row] + ERRF);
    const float4* kp = reinterpret_cast<const float4*>(k + (size_t)row * DIM + q * 16);

    __half2 oh[8], ol[8], ob[8];
    #pragma unroll
    for (int p = 0; p < 4; ++p) {
        float4 v = kp[p];
        float a0 = v.x * ws, a1 = v.y * ws, a2 = v.z * ws, a3 = v.w * ws;
        __half h0 = __float2half_rn(a0), h1 = __float2half_rn(a1);
        __half h2 = __float2half_rn(a2), h3 = __float2half_rn(a3);
        oh[p * 2]     = __half2(h0, h1);
        oh[p * 2 + 1] = __half2(h2, h3);
        ol[p * 2]     = __floats2half2_rn(a0 - __half2float(h0), a1 - __half2float(h1));
        ol[p * 2 + 1] = __floats2half2_rn(a2 - __half2float(h2), a3 - __half2float(h3));
        ob[p * 2]     = __floats2half2_rn(v.x * wd, v.y * wd);
        ob[p * 2 + 1] = __floats2half2_rn(v.z * wd, v.w * wd);
    }
    const size_t o = (size_t)row * DIM + q * 16;
    uint4* dAh = reinterpret_cast<uint4*>(g_Ah + o);
    uint4* dAl = reinterpret_cast<uint4*>(g_Al + o);
    uint4* dBh = reinterpret_cast<uint4*>(g_Bh + o);
    const uint4* sh = reinterpret_cast<const uint4*>(oh);
    const uint4* sl = reinterpret_cast<const uint4*>(ol);
    const uint4* sb = reinterpret_cast<const uint4*>(ob);
    dAh[0] = sh[0]; dAh[1] = sh[1];
    dAl[0] = sl[0]; dAl[1] = sl[1];
    dBh[0] = sb[0]; dBh[1] = sb[1];
}

// B tile copy with column-coalescing row permutation:
// within each 16-row group, true row t -> position [0,1,8,9,2,3,10,11,4,5,12,13,6,7,14,15]
__device__ __forceinline__ void cp_tile16_perm(const char* gsrc, unsigned sdst, int tid) {
    #pragma unroll
    for (int i = 0; i < 8; ++i) {
        int cid = tid + 128 * i;
        int row = cid >> 3;
        int pr  = (row & ~15) | ((row & 2) << 2) | ((row >> 1) & 6) | (row & 1);
        unsigned dst = (unsigned)(pr * 128 + (cid & 7) * 16);
        cp16(sdst + SWZ(dst), gsrc + (unsigned)(cid << 4));
    }
}
// A tile (8KB, 64 rows), no permutation
__device__ __forceinline__ void cp_tile8(const char* gsrc, unsigned sdst, int tid) {
    #pragma unroll
    for (int i = 0; i < 4; ++i) {
        int cid = tid + 128 * i;
        unsigned off = (unsigned)(cid << 4);
        cp16(sdst + SWZ(off), gsrc + off);
    }
}

// ---------------- main kernel: 128 threads, 64-row i-tile, 4 CTAs/SM ----------------
__global__ void __launch_bounds__(128, 4)
mha_hmma12_kernel(float* __restrict__ out)
{
    extern __shared__ char smem[];
    const int tid = threadIdx.x;
    const int wid = tid >> 5;
    const int lid = tid & 31;
    const int bh  = blockIdx.y;
    const int diag = blockIdx.x >> 1;
    const int it0 = blockIdx.x * 64;

    float* ob = out + (size_t)bh * LEN * LEN;
    const char* gA  = reinterpret_cast<const char*>(g_Ah + ((size_t)bh * LEN + it0) * DIM);
    const char* gAl = reinterpret_cast<const char*>(g_Al + ((size_t)bh * LEN + it0) * DIM);
    const char* gB  = reinterpret_cast<const char*>(g_Bh + (size_t)bh * LEN * DIM);

    const unsigned sbase = smem_u32(smem);

    cp_tile8(gA,  sbase, tid);
    cp_tile8(gAl, sbase + OFF_ALO, tid);
    cp_tile16_perm(gB, sbase + OFF_B, tid);
    cp_commit();
    cp_wait0();
    __syncthreads();

    // ldmatrix lane addressing
    const int l7  = lid & 7;
    const int sel = lid >> 3;
    const unsigned xk = (unsigned)(l7 << 4);
    const int arow  = wid * 16 + l7 + ((sel & 1) ? 8 : 0);
    const unsigned akoff = (sel & 2) ? 16u : 0u;
    const int bn    = l7 + ((sel & 2) ? 8 : 0);
    const unsigned bkoff = (sel & 1) ? 16u : 0u;
    const unsigned a_lane = sbase + (unsigned)(arow * 128);
    const unsigned b_lane = sbase + OFF_B + (unsigned)(bn * 128);

    // A fragments register-resident (lo used only on the diagonal tile)
    unsigned ah[4][4], al[4][4];
    #pragma unroll
    for (int ks = 0; ks < 4; ++ks) {
        const unsigned ak = ((unsigned)(ks * 32) + akoff) ^ xk;
        ldsm4(a_lane + ak, ah[ks][0], ah[ks][1], ah[ks][2], ah[ks][3]);
        ldsm4(a_lane + OFF_ALO + ak, al[ks][0], al[ks][1], al[ks][2], al[ks][3]);
    }

    // epilogue lane mapping: for fragment pair (2m,2m+1), lane q owns TRUE cols 16m+4q..+3
    const int q  = lid & 3;
    const int g4 = lid >> 2;
    const int gi_lo = it0 + wid * 16 + g4;
    const int gi_hi = gi_lo + 8;
    float* const row_lo = ob + (size_t)gi_lo * LEN;
    float* const row_hi = ob + (size_t)gi_hi * LEN;

    float carry_lo = 0.f, carry_hi = 0.f;
    float part_lo = 0.f,  part_hi = 0.f;

    for (int jt = 0; jt < NT; ++jt) {
        const int jb0 = jt * 128;
        const bool below = (jt < diag);
        const int nxt = jt + 1;

        if (nxt < NT) {
            cp_tile16_perm(gB + (size_t)nxt * 16384, sbase + OFF_B + (nxt & 1) * 16384, tid);
            cp_commit();
        }

        // zero-fill stores for fully-masked tiles (streaming, row-contiguous)
        if (below) {
            float* base = ob + (size_t)(it0 + wid * 16) * LEN + jb0 + lid * 4;
            #pragma unroll
            for (int r = 0; r < 16; ++r)
                stcs4_zero(base + (size_t)r * LEN);
        }

        float c[16][4];
        const unsigned bbuf = (unsigned)((jt & 1) * 16384);
        if (jt != diag) {
            // hi-only single pass: error feeds either masked zeros' carry or
            // large-baseline cumsum terms -> well inside rel_err budget
            #pragma unroll
            for (int ks = 0; ks < 4; ++ks) {
                const unsigned bkb = ((unsigned)(ks * 32) + bkoff) ^ xk;
                #pragma unroll
                for (int np = 0; np < 8; ++np) {
                    unsigned b0, b1, b2, b3;
                    ldsm4(b_lane + bbuf + (unsigned)(np * 2048) + bkb, b0, b1, b2, b3);
                    if (ks == 0) {
                        mma16816_z(c[np * 2],     ah[0], b0, b1);
                        mma16816_z(c[np * 2 + 1], ah[0], b2, b3);
                    } else {
                        mma16816(c[np * 2],     ah[ks], b0, b1);
                        mma16816(c[np * 2 + 1], ah[ks], b2, b3);
                    }
                }
            }
        } else {
            // diagonal tile: 2-pass fp16 split (protects smallest cumsum baselines)
            #pragma unroll
            for (int ks = 0; ks < 4; ++ks) {
                const unsigned bkb = ((unsigned)(ks * 32) + bkoff) ^ xk;
                #pragma unroll
                for (int np = 0; np < 8; ++np) {
                    unsigned b0, b1, b2, b3;
                    ldsm4(b_lane + bbuf + (unsigned)(np * 2048) + bkb, b0, b1, b2, b3);
                    if (ks == 0) {
                        mma16816_z(c[np * 2],     ah[0], b0, b1);
                        mma16816_z(c[np * 2 + 1], ah[0], b2, b3);
                    } else {
                        mma16816(c[np * 2],     ah[ks], b0, b1);
                        mma16816(c[np * 2 + 1], ah[ks], b2, b3);
                    }
                    mma16816(c[np * 2],     al[ks], b0, b1);
                    mma16816(c[np * 2 + 1], al[ks], b2, b3);
                }
            }
        }

        // lane-partials -> full-row carry at the diagonal tile
        if (jt == diag) {
            float v = part_lo;
            v += __shfl_xor_sync(0xffffffffu, v, 1, 4);
            v += __shfl_xor_sync(0xffffffffu, v, 2, 4);
            carry_lo = v;
            v = part_hi;
            v += __shfl_xor_sync(0xffffffffu, v, 1, 4);
            v += __shfl_xor_sync(0xffffffffu, v, 2, 4);
            carry_hi = v;
        }

        // ---- batched epilogue: stage A = independent scans, stage B = carry + stores ----
        auto epi_group = [&](int g, bool masked) {
            float totl[4], toth[4];
            #pragma unroll
            for (int mm = 0; mm < 4; ++mm) {
                const int m = g * 4 + mm;
                float t0 = pow23(c[2 * m][0]), t1 = pow23(c[2 * m][1]);
                float t2 = pow23(c[2 * m + 1][0]), t3 = pow23(c[2 * m + 1][1]);
                float s = t0 + t1 + t2 + t3, p = s, o;
                o = __shfl_up_sync(0xffffffffu, p, 1, 4); if (q >= 1) p += o;
                o = __shfl_up_sync(0xffffffffu, p, 2, 4); if (q >= 2) p += o;
                totl[mm] = __shfl_sync(0xffffffffu, p, 3, 4);
                float e = p - s;
                float w0 = e + t0, w1 = w0 + t1, w2 = w1 + t2, w3 = w2 + t3;
                c[2 * m][0] = w0; c[2 * m][1] = w1;
                c[2 * m + 1][0] = w2; c[2 * m + 1][1] = w3;
            }
            #pragma unroll
            for (int mm = 0; mm < 4; ++mm) {
                const int m = g * 4 + mm;
                const int col0 = jb0 + m * 16 + q * 4;
                float o0 = carry_lo + c[2 * m][0];
                float o1 = carry_lo + c[2 * m][1];
                float o2 = carry_lo + c[2 * m + 1][0];
                float o3 = carry_lo + c[2 * m + 1][1];
                carry_lo += totl[mm];
                float4 st = masked ? make_float4(col0 >= gi_lo ? o0 : 0.f,
                                                 col0 + 1 >= gi_lo ? o1 : 0.f,
                                                 col0 + 2 >= gi_lo ? o2 : 0.f,
                                                 col0 + 3 >= gi_lo ? o3 : 0.f)
                                   : make_float4(o0, o1, o2, o3);
                stcs4(row_lo + col0, st);
            }
            #pragma unroll
            for (int mm = 0; mm < 4; ++mm) {
                const int m = g * 4 + mm;
                float t0 = pow23(c[2 * m][2]), t1 = pow23(c[2 * m][3]);
                float t2 = pow23(c[2 * m + 1][2]), t3 = pow23(c[2 * m + 1][3]);
                float s = t0 + t1 + t2 + t3, p = s, o;
                o = __shfl_up_sync(0xffffffffu, p, 1, 4); if (q >= 1) p += o;
                o = __shfl_up_sync(0xffffffffu, p, 2, 4); if (q >= 2) p += o;
                toth[mm] = __shfl_sync(0xffffffffu, p, 3, 4);
                float e = p - s;
                float w0 = e + t0, w1 = w0 + t1, w2 = w1 + t2, w3 = w2 + t3;
                c[2 * m][2] = w0; c[2 * m][3] = w1;
                c[2 * m + 1][2] = w2; c[2 * m + 1][3] = w3;
            }
            #pragma unroll
            for (int mm = 0; mm < 4; ++mm) {
                const int m = g * 4 + mm;
                const int col0 = jb0 + m * 16 + q * 4;
                float o0 = carry_hi + c[2 * m][2];
                float o1 = carry_hi + c[2 * m][3];
                float o2 = carry_hi + c[2 * m + 1][2];
                float o3 = carry_hi + c[2 * m + 1][3];
                carry_hi += toth[mm];
                float4 st = masked ? make_float4(col0 >= gi_hi ? o0 : 0.f,
                                                 col0 + 1 >= gi_hi ? o1 : 0.f,
                                                 col0 + 2 >= gi_hi ? o2 : 0.f,
                                                 col0 + 3 >= gi_hi ? o3 : 0.f)
                                   : make_float4(o0, o1, o2, o3);
                stcs4(row_hi + col0, st);
            }
        };

        auto accum_only = [&](int nb) {
            part_lo += pow23(c[nb][0]) + pow23(c[nb][1]);
            part_hi += pow23(c[nb][2]) + pow23(c[nb][3]);
        };

        if (below) {
            #pragma unroll
            for (int nb = 0; nb < 16; ++nb) accum_only(nb);
        } else if (jt == diag) {
            epi_group(0, true);
            epi_group(1, true);
        } else {
            epi_group(0, false);
            epi_group(1, false);
        }

        if (nxt < NT) cp_wait0();
        __syncthreads();
    }
}

extern "C" void kernel_launch(void* const* d_in, const int* in_sizes, int n_in,
                              void* d_out, int out_size) {
    const float* k   = (const float*)d_in[0];
    const float* src = (const float*)d_in[1];
    const float* dst = (const float*)d_in[2];
    float*       out = (float*)d_out;

    cudaFuncSetAttribute(mha_hmma12_kernel,
                         cudaFuncAttributeMaxDynamicSharedMemorySize, SMEM_TOTAL);
    (void)in_sizes; (void)n_in; (void)out_size;

    prep_kernel<<<BHN * LEN * 4 / 256, 256>>>(k, src, dst);
    dim3 grid(LEN / 64, BHN);
    mha_hmma12_kernel<<<grid, 128, SMEM_TOTAL>>>(out);
}